// round 16
// baseline (speedup 1.0000x reference)
#include <cuda_runtime.h>
#include <cstdint>

#define NI 2000     // inner tree nodes
#define NL 10000    // leaves / vocab
#define ND 128      // docs
#define KC 80       // dims per dist chunk
#define KC4 (KC/4)  // 20 float4 per row
#define KC2 (KC/2)  // 40 float2 per row
#define SROW2 41    // smem row stride in float2 (odd -> conflict-free b-loads)
#define NCH_P 25    // proj chunks (2000/80)
#define NCH_M 125   // mass chunks (10000/80)
#define RCH 16      // argmax row chunks (125 rows each)
#define NARG 160    // argmax CTAs (10 x 16)
#define PPARTS 4    // leaf partitions per doc for proj scatter
#define PLEAF (NL/PPARTS)   // 2500 leaves per partition

#define ADD_F32X2(out, a, b) \
    asm("add.rn.f32x2 %0, %1, %2;" : "=l"(out) : "l"(a), "l"(b))

// ---- scratch (static __device__, no allocation) ----
__device__ __align__(16) float g_pmax[RCH * NL];
__device__ __align__(16) int   g_pidx[RCH * NL];
__device__ __align__(16) int   g_arg[NL];
__device__ __align__(16) float g_proj[ND * NI];

// ---------------------------------------------------------------------------
// Device helper: one 64x64 L1-distance tile accumulation into out (atomics).
// ---------------------------------------------------------------------------
__device__ __forceinline__ void dist_tile(const float* __restrict__ src,
                                          int stride, int d0, int tile,
                                          float* __restrict__ out,
                                          float2* shP, float2* shQ) {
    int tp = (tile == 2) ? 1 : 0;
    int tq = (tile == 0) ? 0 : 1;
    int p0 = tp * 64, q0 = tq * 64;

    int tid = threadIdx.x;
    int tx = tid & 15, ty = tid >> 4;

    for (int i4 = tid; i4 < 64 * KC4; i4 += 256) {
        int row = i4 / KC4, k4 = i4 % KC4;
        const float4* gp = (const float4*)(src + (size_t)(p0 + row) * stride + d0);
        const float4* gq = (const float4*)(src + (size_t)(q0 + row) * stride + d0);
        float4 vp = gp[k4];
        float4 vq = gq[k4];
        shP[row * SROW2 + 2 * k4    ] = make_float2(vp.x, vp.y);
        shP[row * SROW2 + 2 * k4 + 1] = make_float2(vp.z, vp.w);
        shQ[row * SROW2 + 2 * k4    ] = make_float2(-vq.x, -vq.y);
        shQ[row * SROW2 + 2 * k4 + 1] = make_float2(-vq.z, -vq.w);
    }
    __syncthreads();

    const uint64_t* sp8 = (const uint64_t*)shP;
    const uint64_t* sq8 = (const uint64_t*)shQ;
    const uint64_t ABSM = 0x7FFFFFFF7FFFFFFFull;

    uint64_t acc2[4][4] = {};
#pragma unroll 2
    for (int k2 = 0; k2 < KC2; k2++) {
        uint64_t a2[4], b2[4];
#pragma unroll
        for (int i = 0; i < 4; i++) a2[i] = sp8[(ty + 16 * i) * SROW2 + k2];
#pragma unroll
        for (int j = 0; j < 4; j++) b2[j] = sq8[(tx + 16 * j) * SROW2 + k2];
#pragma unroll
        for (int i = 0; i < 4; i++)
#pragma unroll
            for (int j = 0; j < 4; j++) {
                uint64_t d;
                ADD_F32X2(d, a2[i], b2[j]);   // a - b (b pre-negated)
                d &= ABSM;                    // packed |.| (alu pipe)
                ADD_F32X2(acc2[i][j], acc2[i][j], d);
            }
    }

#pragma unroll
    for (int i = 0; i < 4; i++) {
        int p = p0 + ty + 16 * i;
#pragma unroll
        for (int j = 0; j < 4; j++) {
            int q = q0 + tx + 16 * j;
            float flo = __uint_as_float((unsigned)(acc2[i][j] & 0xFFFFFFFFu));
            float fhi = __uint_as_float((unsigned)(acc2[i][j] >> 32));
            float v = flo + fhi;
            atomicAdd(&out[p * ND + q], v);
            if (tile == 1) atomicAdd(&out[q * ND + p], v);   // mirror
        }
    }
}

// ---------------------------------------------------------------------------
// K0: zero d_out and g_proj (atomic-accumulate targets).
// ---------------------------------------------------------------------------
__global__ __launch_bounds__(256) void zero_kernel(float* __restrict__ out) {
    int gtid = blockIdx.x * 256 + threadIdx.x;
    for (int i = gtid; i < ND * ND; i += 64 * 256) out[i] = 0.f;
    for (int i = gtid; i < ND * NI; i += 64 * 256) g_proj[i] = 0.f;
}

// ---------------------------------------------------------------------------
// K1 fused: bid < NARG -> argmax role (DRAM-bound, critical path, low bids);
//           bid >= NARG -> mass-dist role (fma/L1-bound). Independent work,
//           complementary bottlenecks, co-scheduled without streams.
// ---------------------------------------------------------------------------
__global__ __launch_bounds__(256) void fused_argmax_distmass(
        const float* __restrict__ param, const float* __restrict__ mass,
        float* __restrict__ out) {
    __shared__ __align__(16) float2 shP[64 * SROW2];
    __shared__ __align__(16) float2 shQ[64 * SROW2];

    int bid = blockIdx.x;
    if (bid < NARG) {
        // ---- argmax role: 10 x 16 layout ----
        int c4 = (bid % 10) * 256 + threadIdx.x;   // float4 column 0..2499
        if (c4 >= NL / 4) return;
        int chunk = bid / 10;
        int r0 = chunk * 125;
        const float4* p = (const float4*)(param + (size_t)r0 * NL) + c4;
        float4 m = p[0];
        int4 mi = make_int4(r0, r0, r0, r0);
#pragma unroll 4
        for (int r = 1; r < 125; r++) {
            float4 v = p[(size_t)r * (NL / 4)];
            if (v.x > m.x) { m.x = v.x; mi.x = r0 + r; }
            if (v.y > m.y) { m.y = v.y; mi.y = r0 + r; }
            if (v.z > m.z) { m.z = v.z; mi.z = r0 + r; }
            if (v.w > m.w) { m.w = v.w; mi.w = r0 + r; }
        }
        ((float4*)g_pmax)[chunk * (NL / 4) + c4] = m;
        ((int4*)g_pidx)[chunk * (NL / 4) + c4] = mi;
    } else {
        // ---- mass-dist role: 375 CTAs over (tile, chunk) ----
        int idx = bid - NARG;
        int tile = idx % 3;
        int chunk = idx / 3;             // 0..124 over mass dims
        dist_tile(mass, NL, chunk * KC, tile, out, shP, shQ);
    }
}

__global__ __launch_bounds__(256) void argmax_reduce() {
    int c4 = blockIdx.x * 256 + threadIdx.x;
    if (c4 >= NL / 4) return;
    float4 m = ((float4*)g_pmax)[c4];
    int4 mi = ((int4*)g_pidx)[c4];
#pragma unroll
    for (int c = 1; c < RCH; c++) {
        float4 v = ((float4*)g_pmax)[c * (NL / 4) + c4];
        int4 vi = ((int4*)g_pidx)[c * (NL / 4) + c4];
        if (v.x > m.x) { m.x = v.x; mi.x = vi.x; }
        if (v.y > m.y) { m.y = v.y; mi.y = vi.y; }
        if (v.z > m.z) { m.z = v.z; mi.z = vi.z; }
        if (v.w > m.w) { m.w = v.w; mi.w = vi.w; }
    }
    ((int4*)g_arg)[c4] = mi;
}

// ---------------------------------------------------------------------------
// K3: scatter + tree-sum + atomic merge. grid (ND, PPARTS).
// ---------------------------------------------------------------------------
__global__ __launch_bounds__(256) void proj_scatter_tree(const float* __restrict__ mass) {
    __shared__ float s[NI];
    int d = blockIdx.x;
    int part = blockIdx.y;
    int tid = threadIdx.x;
    for (int i = tid; i < NI; i += 256) s[i] = 0.f;
    __syncthreads();

    const float* mrow = mass + (size_t)d * NL + part * PLEAF;
    const int*   arow = g_arg + part * PLEAF;

    float v[10];
    int   a[10];
#pragma unroll
    for (int it = 0; it < 10; it++) {        // independent loads first (MLP)
        int l = tid + it * 256;
        if (l < PLEAF) { v[it] = mrow[l]; a[it] = arow[l]; }
    }
#pragma unroll
    for (int it = 0; it < 10; it++) {
        int l = tid + it * 256;
        if (l < PLEAF) atomicAdd(&s[a[it]], v[it]);
    }
    __syncthreads();

    const int lo[5] = {156, 31, 6, 1, 0};
    const int hi[5] = {399, 155, 30, 5, 0};
#pragma unroll
    for (int ph = 0; ph < 5; ph++) {
        for (int r = lo[ph] + tid; r <= hi[ph]; r += 256) {
            int c0 = 5 * r + 1;
            float acc = s[r] + s[c0] + s[c0 + 1] + s[c0 + 2] + s[c0 + 3];
            if (c0 + 4 < NI) acc += s[c0 + 4];   // node 399 has 4 children
            s[r] = acc;
        }
        __syncthreads();
    }
    float* dst = g_proj + (size_t)d * NI;
    for (int i = tid; i < NI; i += 256)
        atomicAdd(&dst[i], s[i]);
}

// ---------------------------------------------------------------------------
// K4: proj-part pairwise L1 (75 CTAs).
// ---------------------------------------------------------------------------
__global__ __launch_bounds__(256) void dist_proj(float* __restrict__ out) {
    __shared__ __align__(16) float2 shP[64 * SROW2];
    __shared__ __align__(16) float2 shQ[64 * SROW2];
    int tile = blockIdx.x;
    int chunk = blockIdx.y;          // 0..24 over proj dims
    dist_tile(g_proj, NI, chunk * KC, tile, out, shP, shQ);
}

// ---------------------------------------------------------------------------
extern "C" void kernel_launch(void* const* d_in, const int* in_sizes, int n_in,
                              void* d_out, int out_size) {
    const float* mass  = (const float*)d_in[0];
    const float* param = (const float*)d_in[1];
    if (n_in >= 2 && in_sizes[0] == NI * NL) {   // robust to input ordering
        param = (const float*)d_in[0];
        mass  = (const float*)d_in[1];
    }
    float* out = (float*)d_out;

    zero_kernel<<<64, 256>>>(out);
    fused_argmax_distmass<<<NARG + 3 * NCH_M, 256>>>(param, mass, out);
    argmax_reduce<<<10, 256>>>();
    proj_scatter_tree<<<dim3(ND, PPARTS), 256>>>(mass);
    dist_proj<<<dim3(3, NCH_P), 256>>>(out);
}